// round 1
// baseline (speedup 1.0000x reference)
#include <cuda_runtime.h>

#define ALPHA 0.2f

// Aggregated edge features scratch: [128*75, 192] = 7.37 MB (static, allowed)
static __device__ float g_agg[9600 * 192];

__device__ __forceinline__ float lrelu(float v) { return v > 0.0f ? v : ALPHA * v; }

// ---------------- Edge kernel: one CTA per (b, i) ----------------
// SMEM layout (floats):
#define O_W1 0        // 7*96   = 672
#define O_W2 672      // 96*160 = 15360
#define O_W3 16032    // 160*192= 30720
#define O_B2 46752    // 160
#define O_B3 46912    // 192
#define O_UI 47104    // 96   (b1 + x_i @ W1[0:3])
#define O_XJ 47200    // 75*3 (pad to 228)
#define O_D  47428    // 75   (pad to 76)
#define O_H1 47504    // 25 rows * stride 100 = 2500
#define O_H2 50004    // 25 rows * stride 164 = 4100
#define O_AG 54104    // 192
#define SMEM1_FL 54296
#define SMEM1_BYTES (SMEM1_FL * 4)

__global__ void __launch_bounds__(256, 1)
edge_kernel(const float* __restrict__ x,
            const float* __restrict__ w1, const float* __restrict__ b1,
            const float* __restrict__ w2, const float* __restrict__ b2,
            const float* __restrict__ w3, const float* __restrict__ b3)
{
    extern __shared__ float s[];
    const int tid = threadIdx.x;

    // Cooperative weight load (all counts divisible by 4, global ptrs 256B aligned)
    {
        float4* d; const float4* g;
        d = (float4*)(s + O_W1); g = (const float4*)w1;
        for (int i = tid; i < 672 / 4; i += 256) d[i] = g[i];
        d = (float4*)(s + O_W2); g = (const float4*)w2;
        for (int i = tid; i < 15360 / 4; i += 256) d[i] = g[i];
        d = (float4*)(s + O_W3); g = (const float4*)w3;
        for (int i = tid; i < 30720 / 4; i += 256) d[i] = g[i];
        d = (float4*)(s + O_B2); g = (const float4*)b2;
        for (int i = tid; i < 160 / 4; i += 256) d[i] = g[i];
        d = (float4*)(s + O_B3); g = (const float4*)b3;
        for (int i = tid; i < 192 / 4; i += 256) d[i] = g[i];
    }

    const int bi = blockIdx.x;            // 0..9599
    const int b = bi / 75, i = bi % 75;
    const float* xb = x + b * 75 * 3;
    const float xi0 = xb[i * 3 + 0], xi1 = xb[i * 3 + 1], xi2 = xb[i * 3 + 2];

    if (tid < 75) {
        float a0 = xb[tid * 3 + 0], a1 = xb[tid * 3 + 1], a2 = xb[tid * 3 + 2];
        s[O_XJ + 3 * tid + 0] = a0;
        s[O_XJ + 3 * tid + 1] = a1;
        s[O_XJ + 3 * tid + 2] = a2;
        // reference: norm(diff + 1e-12) -> 1e-12 added per component BEFORE square
        float d0 = (a0 - xi0) + 1e-12f;
        float d1 = (a1 - xi1) + 1e-12f;
        float d2 = (a2 - xi2) + 1e-12f;
        s[O_D + tid] = sqrtf(d0 * d0 + d1 * d1 + d2 * d2);
    }
    if (tid < 192) s[O_AG + tid] = 0.0f;
    __syncthreads();

    // U_i[c] = b1[c] + x_i @ W1[0:3, c]
    if (tid < 96)
        s[O_UI + tid] = b1[tid] + xi0 * s[O_W1 + tid]
                                + xi1 * s[O_W1 + 96 + tid]
                                + xi2 * s[O_W1 + 192 + tid];
    __syncthreads();

    float agg0 = 0.f, agg1 = 0.f, agg2 = 0.f, agg3 = 0.f;   // per-thread column partials
    const int cg3 = tid % 48, rg3 = tid / 48;               // L3 mapping (240 threads)

    for (int t = 0; t < 3; t++) {
        const int j0 = t * 25;

        // ---- Layer 1: h1[25][96] = lrelu(U_i + x_j@W1[3:6] + dist*W1[6]) ----
        for (int idx = tid; idx < 25 * 96; idx += 256) {
            int r = idx / 96, c = idx - r * 96;
            int j = j0 + r;
            float v = s[O_UI + c]
                    + s[O_XJ + 3 * j + 0] * s[O_W1 + 288 + c]
                    + s[O_XJ + 3 * j + 1] * s[O_W1 + 384 + c]
                    + s[O_XJ + 3 * j + 2] * s[O_W1 + 480 + c]
                    + s[O_D + j]          * s[O_W1 + 576 + c];
            s[O_H1 + r * 100 + c] = lrelu(v);
        }
        __syncthreads();

        // ---- Layer 2: h2[25][160] = lrelu(h1 @ W2 + b2), 200 threads, 5x4 tile ----
        if (tid < 200) {
            int cg = tid % 40, rg = tid / 40;
            int c0 = cg * 4, r0 = rg * 5;
            float acc[5][4];
            #pragma unroll
            for (int m = 0; m < 5; m++)
                { acc[m][0]=0.f; acc[m][1]=0.f; acc[m][2]=0.f; acc[m][3]=0.f; }
            const float* h1b = s + O_H1 + r0 * 100;
            #pragma unroll 4
            for (int k = 0; k < 96; k++) {
                float4 w = *(const float4*)(s + O_W2 + k * 160 + c0);
                #pragma unroll
                for (int m = 0; m < 5; m++) {
                    float h = h1b[m * 100 + k];
                    acc[m][0] += h * w.x; acc[m][1] += h * w.y;
                    acc[m][2] += h * w.z; acc[m][3] += h * w.w;
                }
            }
            float4 bb = *(const float4*)(s + O_B2 + c0);
            #pragma unroll
            for (int m = 0; m < 5; m++) {
                float4 o;
                o.x = lrelu(acc[m][0] + bb.x);
                o.y = lrelu(acc[m][1] + bb.y);
                o.z = lrelu(acc[m][2] + bb.z);
                o.w = lrelu(acc[m][3] + bb.w);
                *(float4*)(s + O_H2 + (r0 + m) * 164 + c0) = o;
            }
        }
        __syncthreads();

        // ---- Layer 3 + aggregation: 240 threads, 5x4 tile, agg kept in registers ----
        if (tid < 240) {
            int c0 = cg3 * 4, r0 = rg3 * 5;
            float acc[5][4];
            #pragma unroll
            for (int m = 0; m < 5; m++)
                { acc[m][0]=0.f; acc[m][1]=0.f; acc[m][2]=0.f; acc[m][3]=0.f; }
            const float* h2b = s + O_H2 + r0 * 164;
            #pragma unroll 4
            for (int k = 0; k < 160; k++) {
                float4 w = *(const float4*)(s + O_W3 + k * 192 + c0);
                #pragma unroll
                for (int m = 0; m < 5; m++) {
                    float h = h2b[m * 164 + k];
                    acc[m][0] += h * w.x; acc[m][1] += h * w.y;
                    acc[m][2] += h * w.z; acc[m][3] += h * w.w;
                }
            }
            float4 bb = *(const float4*)(s + O_B3 + c0);
            #pragma unroll
            for (int m = 0; m < 5; m++) {
                agg0 += lrelu(acc[m][0] + bb.x);
                agg1 += lrelu(acc[m][1] + bb.y);
                agg2 += lrelu(acc[m][2] + bb.z);
                agg3 += lrelu(acc[m][3] + bb.w);
            }
        }
        __syncthreads();   // protect H1/H2 before next tile overwrites
    }

    if (tid < 240) {
        int c0 = cg3 * 4;
        atomicAdd(&s[O_AG + c0 + 0], agg0);
        atomicAdd(&s[O_AG + c0 + 1], agg1);
        atomicAdd(&s[O_AG + c0 + 2], agg2);
        atomicAdd(&s[O_AG + c0 + 3], agg3);
    }
    __syncthreads();
    if (tid < 192) g_agg[bi * 192 + tid] = s[O_AG + tid];
}

// ---------------- Node kernel: one CTA per 32 rows ----------------
#define O2_Y 0         // 32 * 200 = 6400 (195 used)
#define O2_H 6400      // 32 * 260 = 8320
#define O2_W 14720     // up to 65*256 = 16640
#define SMEM2_FL 31360
#define SMEM2_BYTES (SMEM2_FL * 4)

__global__ void __launch_bounds__(256, 1)
node_kernel(const float* __restrict__ x,
            const float* __restrict__ w1, const float* __restrict__ b1,
            const float* __restrict__ w2, const float* __restrict__ b2,
            const float* __restrict__ w3, const float* __restrict__ b3,
            float* __restrict__ out)
{
    extern __shared__ float s[];
    const int tid = threadIdx.x;
    const int row0 = blockIdx.x * 32;

    // Build y = [agg(192), x(3)] tile in SMEM (stride 200)
    for (int idx = tid; idx < 32 * 192; idx += 256) {
        int r = idx / 192, c = idx - r * 192;
        s[O2_Y + r * 200 + c] = g_agg[(row0 + r) * 192 + c];
    }
    for (int idx = tid; idx < 96; idx += 256) {
        int r = idx / 3, c = idx - r * 3;
        s[O2_Y + r * 200 + 192 + c] = x[(row0 + r) * 3 + c];
    }

    const int cg = tid % 64, rg = tid / 64;
    const int c0 = cg * 4, r0 = rg * 8;

    // ---- Layer 1: [32,195] @ [195,256], K chunks of 65, 8x4 register tile ----
    float acc[8][4];
    #pragma unroll
    for (int m = 0; m < 8; m++)
        { acc[m][0]=0.f; acc[m][1]=0.f; acc[m][2]=0.f; acc[m][3]=0.f; }
    for (int kc = 0; kc < 3; kc++) {
        __syncthreads();
        {   // load W1 chunk [65][256]
            float4* d = (float4*)(s + O2_W);
            const float4* g = (const float4*)(w1 + kc * 65 * 256);
            for (int i = tid; i < (65 * 256) / 4; i += 256) d[i] = g[i];
        }
        __syncthreads();
        const int kbase = kc * 65;
        for (int k = 0; k < 65; k++) {
            float4 w = *(const float4*)(s + O2_W + k * 256 + c0);
            #pragma unroll
            for (int m = 0; m < 8; m++) {
                float h = s[O2_Y + (r0 + m) * 200 + kbase + k];
                acc[m][0] += h * w.x; acc[m][1] += h * w.y;
                acc[m][2] += h * w.z; acc[m][3] += h * w.w;
            }
        }
    }
    __syncthreads();
    {
        float4 bb = *(const float4*)(b1 + c0);
        #pragma unroll
        for (int m = 0; m < 8; m++) {
            float4 o;
            o.x = lrelu(acc[m][0] + bb.x);
            o.y = lrelu(acc[m][1] + bb.y);
            o.z = lrelu(acc[m][2] + bb.z);
            o.w = lrelu(acc[m][3] + bb.w);
            *(float4*)(s + O2_H + (r0 + m) * 260 + c0) = o;
        }
    }

    // ---- Layer 2: [32,256] @ [256,256], K chunks of 64 ----
    float acc2[8][4];
    #pragma unroll
    for (int m = 0; m < 8; m++)
        { acc2[m][0]=0.f; acc2[m][1]=0.f; acc2[m][2]=0.f; acc2[m][3]=0.f; }
    for (int kc = 0; kc < 4; kc++) {
        __syncthreads();
        {
            float4* d = (float4*)(s + O2_W);
            const float4* g = (const float4*)(w2 + kc * 64 * 256);
            for (int i = tid; i < (64 * 256) / 4; i += 256) d[i] = g[i];
        }
        __syncthreads();
        const int kbase = kc * 64;
        for (int k = 0; k < 64; k++) {
            float4 w = *(const float4*)(s + O2_W + k * 256 + c0);
            #pragma unroll
            for (int m = 0; m < 8; m++) {
                float h = s[O2_H + (r0 + m) * 260 + kbase + k];
                acc2[m][0] += h * w.x; acc2[m][1] += h * w.y;
                acc2[m][2] += h * w.z; acc2[m][3] += h * w.w;
            }
        }
    }
    __syncthreads();   // all h1 reads done -> safe to overwrite with h2
    {
        float4 bb = *(const float4*)(b2 + c0);
        #pragma unroll
        for (int m = 0; m < 8; m++) {
            float4 o;
            o.x = lrelu(acc2[m][0] + bb.x);
            o.y = lrelu(acc2[m][1] + bb.y);
            o.z = lrelu(acc2[m][2] + bb.z);
            o.w = lrelu(acc2[m][3] + bb.w);
            *(float4*)(s + O2_H + (r0 + m) * 260 + c0) = o;
        }
    }
    __syncthreads();

    // ---- Layer 3: [32,256] @ [256,3] (linear) ----
    for (int idx = tid; idx < 768; idx += 256) s[O2_W + idx] = w3[idx];
    __syncthreads();
    if (tid < 96) {
        int r = tid / 3, o = tid - r * 3;
        float a = b3[o];
        for (int k = 0; k < 256; k++)
            a += s[O2_H + r * 260 + k] * s[O2_W + k * 3 + o];
        out[(row0 + r) * 3 + o] = a;
    }
}

extern "C" void kernel_launch(void* const* d_in, const int* in_sizes, int n_in,
                              void* d_out, int out_size)
{
    const float* x    = (const float*)d_in[0];
    const float* few1 = (const float*)d_in[1];
    const float* feb1 = (const float*)d_in[2];
    const float* few2 = (const float*)d_in[3];
    const float* feb2 = (const float*)d_in[4];
    const float* few3 = (const float*)d_in[5];
    const float* feb3 = (const float*)d_in[6];
    const float* fnw1 = (const float*)d_in[7];
    const float* fnb1 = (const float*)d_in[8];
    const float* fnw2 = (const float*)d_in[9];
    const float* fnb2 = (const float*)d_in[10];
    const float* fnw3 = (const float*)d_in[11];
    const float* fnb3 = (const float*)d_in[12];
    float* out = (float*)d_out;

    cudaFuncSetAttribute(edge_kernel, cudaFuncAttributeMaxDynamicSharedMemorySize, SMEM1_BYTES);
    cudaFuncSetAttribute(node_kernel, cudaFuncAttributeMaxDynamicSharedMemorySize, SMEM2_BYTES);

    edge_kernel<<<9600, 256, SMEM1_BYTES>>>(x, few1, feb1, few2, feb2, few3, feb3);
    node_kernel<<<300, 256, SMEM2_BYTES>>>(x, fnw1, fnb1, fnw2, fnb2, fnw3, fnb3, out);
}

// round 2
// speedup vs baseline: 1.2255x; 1.2255x over previous
#include <cuda_runtime.h>

#define ALPHA 0.2f

// Aggregated edge features scratch: [128*75, 192] = 7.37 MB (static, allowed)
static __device__ float g_agg[9600 * 192];

__device__ __forceinline__ float lrelu(float v) { return v > 0.0f ? v : ALPHA * v; }

// packed f32x2 FMA: acc.lo += a.lo*b.lo; acc.hi += a.hi*b.hi
#define FFMA2(acc, a, b) \
    asm("fma.rn.f32x2 %0, %1, %2, %0;" : "+l"(acc) : "l"(a), "l"(b))

__device__ __forceinline__ float2 unpack2(unsigned long long v) {
    float2 r;
    asm("mov.b64 {%0, %1}, %2;" : "=f"(r.x), "=f"(r.y) : "l"(v));
    return r;
}

// ---------------- Edge kernel: persistent CTAs, one (b,i) at a time ----------------
// SMEM layout (floats). W2/W3 stored k-pair interleaved:
//   s[O_W2 + (k2*160 + c)*2 + p] = w2[(2*k2+p)*160 + c]
#define O_W1 0        // 7*96   = 672
#define O_W2 672      // 96*160 = 15360 (paired)
#define O_W3 16032    // 160*192= 30720 (paired)
#define O_B2 46752    // 160
#define O_B3 46912    // 192
#define O_UI 47104    // 96   (b1 + x_i @ W1[0:3])
#define O_XJ 47200    // 75*3 (pad to 228)
#define O_D  47428    // 75   (pad to 76)
#define O_H1 47504    // 25 rows * stride 100 = 2500
#define O_H2 50004    // 25 rows * stride 164 = 4100
#define O_AG 54104    // 192
#define SMEM1_FL 54296
#define SMEM1_BYTES (SMEM1_FL * 4)

__global__ void __launch_bounds__(256, 1)
edge_kernel(const float* __restrict__ x,
            const float* __restrict__ w1, const float* __restrict__ b1,
            const float* __restrict__ w2, const float* __restrict__ b2,
            const float* __restrict__ w3, const float* __restrict__ b3)
{
    extern __shared__ float s[];
    const int tid = threadIdx.x;

    // ---- One-time weight load (W2/W3 permuted to k-pair layout) ----
    {
        float4* d; const float4* g;
        d = (float4*)(s + O_W1); g = (const float4*)w1;
        for (int i = tid; i < 672 / 4; i += 256) d[i] = g[i];
        for (int idx = tid; idx < 96 * 160; idx += 256) {
            int k = idx / 160, c = idx - k * 160;
            s[O_W2 + ((k >> 1) * 160 + c) * 2 + (k & 1)] = w2[idx];
        }
        for (int idx = tid; idx < 160 * 192; idx += 256) {
            int k = idx / 192, c = idx - k * 192;
            s[O_W3 + ((k >> 1) * 192 + c) * 2 + (k & 1)] = w3[idx];
        }
        d = (float4*)(s + O_B2); g = (const float4*)b2;
        for (int i = tid; i < 160 / 4; i += 256) d[i] = g[i];
        d = (float4*)(s + O_B3); g = (const float4*)b3;
        for (int i = tid; i < 192 / 4; i += 256) d[i] = g[i];
    }

    // L2 mapping: 200 threads; cols {ca2, ca2+1, cb2, cb2+1}, rows rg2*5..+4
    const int cg2 = tid % 40, rg2 = tid / 40;
    const int ca2 = 2 * cg2, cb2 = 80 + 2 * cg2;
    // L3 mapping: 240 threads
    const int cg3 = tid % 48, rg3 = tid / 48;
    const int ca3 = 2 * cg3, cb3 = 96 + 2 * cg3;

    for (int bi = blockIdx.x; bi < 9600; bi += gridDim.x) {
        const int b = bi / 75, i = bi % 75;
        const float* xb = x + b * 75 * 3;
        const float xi0 = xb[i * 3 + 0], xi1 = xb[i * 3 + 1], xi2 = xb[i * 3 + 2];

        if (tid < 75) {
            float a0 = xb[tid * 3 + 0], a1 = xb[tid * 3 + 1], a2 = xb[tid * 3 + 2];
            s[O_XJ + 3 * tid + 0] = a0;
            s[O_XJ + 3 * tid + 1] = a1;
            s[O_XJ + 3 * tid + 2] = a2;
            float d0 = (a0 - xi0) + 1e-12f;
            float d1 = (a1 - xi1) + 1e-12f;
            float d2 = (a2 - xi2) + 1e-12f;
            s[O_D + tid] = sqrtf(d0 * d0 + d1 * d1 + d2 * d2);
        }
        if (tid < 192) s[O_AG + tid] = 0.0f;
        __syncthreads();   // also covers weight load on first iteration

        // U_i[c] = b1[c] + x_i @ W1[0:3, c]
        if (tid < 96)
            s[O_UI + tid] = b1[tid] + xi0 * s[O_W1 + tid]
                                    + xi1 * s[O_W1 + 96 + tid]
                                    + xi2 * s[O_W1 + 192 + tid];
        __syncthreads();

        float ag0 = 0.f, ag1 = 0.f, ag2 = 0.f, ag3 = 0.f;

        for (int t = 0; t < 3; t++) {
            const int j0 = t * 25;

            // ---- Layer 1: h1[25][96] ----
            for (int idx = tid; idx < 25 * 96; idx += 256) {
                int r = idx / 96, c = idx - r * 96;
                int j = j0 + r;
                float v = s[O_UI + c]
                        + s[O_XJ + 3 * j + 0] * s[O_W1 + 288 + c]
                        + s[O_XJ + 3 * j + 1] * s[O_W1 + 384 + c]
                        + s[O_XJ + 3 * j + 2] * s[O_W1 + 480 + c]
                        + s[O_D + j]          * s[O_W1 + 576 + c];
                s[O_H1 + r * 100 + c] = lrelu(v);
            }
            __syncthreads();

            // ---- Layer 2: h2[25][160] = lrelu(h1 @ W2 + b2), FFMA2 ----
            if (tid < 200) {
                const int r0 = rg2 * 5;
                unsigned long long acc[5][4];
                #pragma unroll
                for (int m = 0; m < 5; m++)
                    { acc[m][0]=0ULL; acc[m][1]=0ULL; acc[m][2]=0ULL; acc[m][3]=0ULL; }
                const float* h1b = s + O_H1 + r0 * 100;
                const float* w2p = s + O_W2;
                #pragma unroll 2
                for (int k2 = 0; k2 < 48; k2++) {
                    ulonglong2 wa = *(const ulonglong2*)(w2p + (k2 * 160 + ca2) * 2);
                    ulonglong2 wb = *(const ulonglong2*)(w2p + (k2 * 160 + cb2) * 2);
                    #pragma unroll
                    for (int m = 0; m < 5; m++) {
                        unsigned long long hp =
                            *(const unsigned long long*)(h1b + m * 100 + 2 * k2);
                        FFMA2(acc[m][0], hp, wa.x);
                        FFMA2(acc[m][1], hp, wa.y);
                        FFMA2(acc[m][2], hp, wb.x);
                        FFMA2(acc[m][3], hp, wb.y);
                    }
                }
                float ba0 = s[O_B2 + ca2], ba1 = s[O_B2 + ca2 + 1];
                float bb0 = s[O_B2 + cb2], bb1 = s[O_B2 + cb2 + 1];
                #pragma unroll
                for (int m = 0; m < 5; m++) {
                    float2 p0 = unpack2(acc[m][0]);
                    float2 p1 = unpack2(acc[m][1]);
                    float2 p2 = unpack2(acc[m][2]);
                    float2 p3 = unpack2(acc[m][3]);
                    float* hr = s + O_H2 + (r0 + m) * 164;
                    hr[ca2]     = lrelu(p0.x + p0.y + ba0);
                    hr[ca2 + 1] = lrelu(p1.x + p1.y + ba1);
                    hr[cb2]     = lrelu(p2.x + p2.y + bb0);
                    hr[cb2 + 1] = lrelu(p3.x + p3.y + bb1);
                }
            }
            __syncthreads();

            // ---- Layer 3 + aggregation, FFMA2 ----
            if (tid < 240) {
                const int r0 = rg3 * 5;
                unsigned long long acc[5][4];
                #pragma unroll
                for (int m = 0; m < 5; m++)
                    { acc[m][0]=0ULL; acc[m][1]=0ULL; acc[m][2]=0ULL; acc[m][3]=0ULL; }
                const float* h2b = s + O_H2 + r0 * 164;
                const float* w3p = s + O_W3;
                #pragma unroll 2
                for (int k2 = 0; k2 < 80; k2++) {
                    ulonglong2 wa = *(const ulonglong2*)(w3p + (k2 * 192 + ca3) * 2);
                    ulonglong2 wb = *(const ulonglong2*)(w3p + (k2 * 192 + cb3) * 2);
                    #pragma unroll
                    for (int m = 0; m < 5; m++) {
                        unsigned long long hp =
                            *(const unsigned long long*)(h2b + m * 164 + 2 * k2);
                        FFMA2(acc[m][0], hp, wa.x);
                        FFMA2(acc[m][1], hp, wa.y);
                        FFMA2(acc[m][2], hp, wb.x);
                        FFMA2(acc[m][3], hp, wb.y);
                    }
                }
                float ba0 = s[O_B3 + ca3], ba1 = s[O_B3 + ca3 + 1];
                float bb0 = s[O_B3 + cb3], bb1 = s[O_B3 + cb3 + 1];
                #pragma unroll
                for (int m = 0; m < 5; m++) {
                    float2 p0 = unpack2(acc[m][0]);
                    float2 p1 = unpack2(acc[m][1]);
                    float2 p2 = unpack2(acc[m][2]);
                    float2 p3 = unpack2(acc[m][3]);
                    ag0 += lrelu(p0.x + p0.y + ba0);
                    ag1 += lrelu(p1.x + p1.y + ba1);
                    ag2 += lrelu(p2.x + p2.y + bb0);
                    ag3 += lrelu(p3.x + p3.y + bb1);
                }
            }
            __syncthreads();   // protect H1/H2 before next tile overwrites
        }

        if (tid < 240) {
            atomicAdd(&s[O_AG + ca3],     ag0);
            atomicAdd(&s[O_AG + ca3 + 1], ag1);
            atomicAdd(&s[O_AG + cb3],     ag2);
            atomicAdd(&s[O_AG + cb3 + 1], ag3);
        }
        __syncthreads();
        if (tid < 192) g_agg[bi * 192 + tid] = s[O_AG + tid];
        __syncthreads();   // O_AG/O_XJ reused next iteration
    }
}

// ---------------- Node kernel: one CTA per 32 rows (unchanged) ----------------
#define O2_Y 0         // 32 * 200 = 6400 (195 used)
#define O2_H 6400      // 32 * 260 = 8320
#define O2_W 14720     // up to 65*256 = 16640
#define SMEM2_FL 31360
#define SMEM2_BYTES (SMEM2_FL * 4)

__global__ void __launch_bounds__(256, 1)
node_kernel(const float* __restrict__ x,
            const float* __restrict__ w1, const float* __restrict__ b1,
            const float* __restrict__ w2, const float* __restrict__ b2,
            const float* __restrict__ w3, const float* __restrict__ b3,
            float* __restrict__ out)
{
    extern __shared__ float s[];
    const int tid = threadIdx.x;
    const int row0 = blockIdx.x * 32;

    for (int idx = tid; idx < 32 * 192; idx += 256) {
        int r = idx / 192, c = idx - r * 192;
        s[O2_Y + r * 200 + c] = g_agg[(row0 + r) * 192 + c];
    }
    for (int idx = tid; idx < 96; idx += 256) {
        int r = idx / 3, c = idx - r * 3;
        s[O2_Y + r * 200 + 192 + c] = x[(row0 + r) * 3 + c];
    }

    const int cg = tid % 64, rg = tid / 64;
    const int c0 = cg * 4, r0 = rg * 8;

    float acc[8][4];
    #pragma unroll
    for (int m = 0; m < 8; m++)
        { acc[m][0]=0.f; acc[m][1]=0.f; acc[m][2]=0.f; acc[m][3]=0.f; }
    for (int kc = 0; kc < 3; kc++) {
        __syncthreads();
        {
            float4* d = (float4*)(s + O2_W);
            const float4* g = (const float4*)(w1 + kc * 65 * 256);
            for (int i = tid; i < (65 * 256) / 4; i += 256) d[i] = g[i];
        }
        __syncthreads();
        const int kbase = kc * 65;
        for (int k = 0; k < 65; k++) {
            float4 w = *(const float4*)(s + O2_W + k * 256 + c0);
            #pragma unroll
            for (int m = 0; m < 8; m++) {
                float h = s[O2_Y + (r0 + m) * 200 + kbase + k];
                acc[m][0] += h * w.x; acc[m][1] += h * w.y;
                acc[m][2] += h * w.z; acc[m][3] += h * w.w;
            }
        }
    }
    __syncthreads();
    {
        float4 bb = *(const float4*)(b1 + c0);
        #pragma unroll
        for (int m = 0; m < 8; m++) {
            float4 o;
            o.x = lrelu(acc[m][0] + bb.x);
            o.y = lrelu(acc[m][1] + bb.y);
            o.z = lrelu(acc[m][2] + bb.z);
            o.w = lrelu(acc[m][3] + bb.w);
            *(float4*)(s + O2_H + (r0 + m) * 260 + c0) = o;
        }
    }

    float acc2[8][4];
    #pragma unroll
    for (int m = 0; m < 8; m++)
        { acc2[m][0]=0.f; acc2[m][1]=0.f; acc2[m][2]=0.f; acc2[m][3]=0.f; }
    for (int kc = 0; kc < 4; kc++) {
        __syncthreads();
        {
            float4* d = (float4*)(s + O2_W);
            const float4* g = (const float4*)(w2 + kc * 64 * 256);
            for (int i = tid; i < (64 * 256) / 4; i += 256) d[i] = g[i];
        }
        __syncthreads();
        const int kbase = kc * 64;
        for (int k = 0; k < 64; k++) {
            float4 w = *(const float4*)(s + O2_W + k * 256 + c0);
            #pragma unroll
            for (int m = 0; m < 8; m++) {
                float h = s[O2_H + (r0 + m) * 260 + kbase + k];
                acc2[m][0] += h * w.x; acc2[m][1] += h * w.y;
                acc2[m][2] += h * w.z; acc2[m][3] += h * w.w;
            }
        }
    }
    __syncthreads();
    {
        float4 bb = *(const float4*)(b2 + c0);
        #pragma unroll
        for (int m = 0; m < 8; m++) {
            float4 o;
            o.x = lrelu(acc2[m][0] + bb.x);
            o.y = lrelu(acc2[m][1] + bb.y);
            o.z = lrelu(acc2[m][2] + bb.z);
            o.w = lrelu(acc2[m][3] + bb.w);
            *(float4*)(s + O2_H + (r0 + m) * 260 + c0) = o;
        }
    }
    __syncthreads();

    for (int idx = tid; idx < 768; idx += 256) s[O2_W + idx] = w3[idx];
    __syncthreads();
    if (tid < 96) {
        int r = tid / 3, o = tid - r * 3;
        float a = b3[o];
        for (int k = 0; k < 256; k++)
            a += s[O2_H + r * 260 + k] * s[O2_W + k * 3 + o];
        out[(row0 + r) * 3 + o] = a;
    }
}

extern "C" void kernel_launch(void* const* d_in, const int* in_sizes, int n_in,
                              void* d_out, int out_size)
{
    const float* x    = (const float*)d_in[0];
    const float* few1 = (const float*)d_in[1];
    const float* feb1 = (const float*)d_in[2];
    const float* few2 = (const float*)d_in[3];
    const float* feb2 = (const float*)d_in[4];
    const float* few3 = (const float*)d_in[5];
    const float* feb3 = (const float*)d_in[6];
    const float* fnw1 = (const float*)d_in[7];
    const float* fnb1 = (const float*)d_in[8];
    const float* fnw2 = (const float*)d_in[9];
    const float* fnb2 = (const float*)d_in[10];
    const float* fnw3 = (const float*)d_in[11];
    const float* fnb3 = (const float*)d_in[12];
    float* out = (float*)d_out;

    cudaFuncSetAttribute(edge_kernel, cudaFuncAttributeMaxDynamicSharedMemorySize, SMEM1_BYTES);
    cudaFuncSetAttribute(node_kernel, cudaFuncAttributeMaxDynamicSharedMemorySize, SMEM2_BYTES);

    edge_kernel<<<148, 256, SMEM1_BYTES>>>(x, few1, feb1, few2, feb2, few3, feb3);
    node_kernel<<<300, 256, SMEM2_BYTES>>>(x, fnw1, fnb1, fnw2, fnb2, fnw3, fnb3, out);
}